// round 2
// baseline (speedup 1.0000x reference)
#include <cuda_runtime.h>

#define NUM_KPT 17
#define BATCH   64
#define HWC     6912           // 96*72
#define HW4     1728           // HWC/4
#define NBK     (BATCH * NUM_KPT)   // 1088
#define N_ELEM  7520256.0f     // 64*17*6912

// scratch: per-(b,k) partials (every slot fully written each launch -> no init needed)
__device__ float g_A[NBK];   // sum (out1_1 - t1)^2
__device__ float g_Bv[NBK];  // sum (o12x*t1 - t2x)^2 + (o12y*t1 - t2y)^2
__device__ float g_P[NBK];   // sum (out2_1 - t1)^2
__device__ float g_Q[NBK];   // sum ((o22x-t2x)^2 + (o22y-t2y)^2) * t1^2
__device__ unsigned int g_count = 0;   // arrival counter; reset by last block each launch

__device__ __forceinline__ float warp_sum(float v) {
    #pragma unroll
    for (int o = 16; o > 0; o >>= 1) v += __shfl_xor_sync(0xffffffffu, v, o);
    return v;
}

__global__ __launch_bounds__(256, 8) void hrp_fused(
    const float* __restrict__ o11, const float* __restrict__ o12,
    const float* __restrict__ o21, const float* __restrict__ o22,
    const float* __restrict__ t1,  const float* __restrict__ t2,
    const float* __restrict__ weights, float* __restrict__ out)
{
    const int bk = blockIdx.x;                 // 0..1087
    const int b  = bk / NUM_KPT;
    const int k  = bk % NUM_KPT;

    const size_t base1 = (size_t)bk * HW4;                          // K-channel tensors
    const size_t basex = ((size_t)b * (2 * NUM_KPT) + k) * HW4;     // 2K tensors, x half
    const size_t basey = basex + (size_t)NUM_KPT * HW4;             // y half

    const float4* O11  = (const float4*)o11 + base1;
    const float4* O21  = (const float4*)o21 + base1;
    const float4* T1   = (const float4*)t1  + base1;
    const float4* O12x = (const float4*)o12 + basex;
    const float4* O12y = (const float4*)o12 + basey;
    const float4* O22x = (const float4*)o22 + basex;
    const float4* O22y = (const float4*)o22 + basey;
    const float4* T2x  = (const float4*)t2  + basex;
    const float4* T2y  = (const float4*)t2  + basey;

    float accA = 0.f, accB = 0.f, accP = 0.f, accQ = 0.f;

    for (int i = threadIdx.x; i < HW4; i += 256) {
        float4 v11  = O11[i];
        float4 vt1  = T1[i];
        float4 v21  = O21[i];
        float4 v12x = O12x[i];
        float4 v12y = O12y[i];
        float4 v22x = O22x[i];
        float4 v22y = O22y[i];
        float4 vt2x = T2x[i];
        float4 vt2y = T2y[i];

        const float* p11  = &v11.x;
        const float* pt1  = &vt1.x;
        const float* p21  = &v21.x;
        const float* p12x = &v12x.x;
        const float* p12y = &v12y.x;
        const float* p22x = &v22x.x;
        const float* p22y = &v22y.x;
        const float* pt2x = &vt2x.x;
        const float* pt2y = &vt2y.x;

        #pragma unroll
        for (int l = 0; l < 4; l++) {
            float t  = pt1[l];
            float d1 = p11[l] - t;                 accA = fmaf(d1, d1, accA);
            float ex = fmaf(p12x[l], t, -pt2x[l]); accB = fmaf(ex, ex, accB);
            float ey = fmaf(p12y[l], t, -pt2y[l]); accB = fmaf(ey, ey, accB);
            float d2 = p21[l] - t;                 accP = fmaf(d2, d2, accP);
            float fx = p22x[l] - pt2x[l];
            float fy = p22y[l] - pt2y[l];
            float s  = fmaf(fx, fx, fy * fy);
            accQ = fmaf(s, t * t, accQ);
        }
    }

    // block reduce (8 warps)
    __shared__ float sA[8], sB[8], sP[8], sQ[8];
    accA = warp_sum(accA); accB = warp_sum(accB);
    accP = warp_sum(accP); accQ = warp_sum(accQ);
    const int wid = threadIdx.x >> 5, lid = threadIdx.x & 31;
    if (lid == 0) { sA[wid] = accA; sB[wid] = accB; sP[wid] = accP; sQ[wid] = accQ; }
    __syncthreads();

    __shared__ bool isLast;
    if (threadIdx.x == 0) {
        float a = 0.f, bb = 0.f, p = 0.f, q = 0.f;
        #pragma unroll
        for (int w = 0; w < 8; w++) { a += sA[w]; bb += sB[w]; p += sP[w]; q += sQ[w]; }
        g_A[bk] = a; g_Bv[bk] = bb; g_P[bk] = p; g_Q[bk] = q;
        __threadfence();                       // publish partials before arrival
        unsigned int prev = atomicAdd(&g_count, 1u);
        isLast = (prev == NBK - 1u);
    }
    __syncthreads();
    if (!isLast) return;

    // ---- final reduction: only the last-arriving block runs this ----
    const int t = threadIdx.x;

    float a = 0.f, bb = 0.f;
    for (int i = t; i < NBK; i += 256) { a += g_A[i]; bb += g_Bv[i]; }

    float l21 = 0.f, l22 = 0.f;
    if (t < BATCH) {
        float pv[NUM_KPT];
        bool used[NUM_KPT];
        #pragma unroll
        for (int kk = 0; kk < NUM_KPT; kk++) { pv[kk] = g_P[t * NUM_KPT + kk]; used[kk] = false; }
        // top-8 selection (largest values, first index on ties — matches jax.lax.top_k)
        #pragma unroll
        for (int r = 0; r < NUM_KPT / 2; r++) {
            int best = -1; float bm = -3.4e38f;
            #pragma unroll
            for (int kk = 0; kk < NUM_KPT; kk++)
                if (!used[kk] && pv[kk] > bm) { bm = pv[kk]; best = kk; }
            used[best] = true;
            l21 += pv[best];
            l22 += g_Q[t * NUM_KPT + best];
        }
    }

    __shared__ float rA[256], rB[256], r21[256], r22[256];
    rA[t] = a; rB[t] = bb; r21[t] = l21; r22[t] = l22;
    __syncthreads();
    #pragma unroll
    for (int s = 128; s > 0; s >>= 1) {
        if (t < s) {
            rA[t]  += rA[t + s];
            rB[t]  += rB[t + s];
            r21[t] += r21[t + s];
            r22[t] += r22[t + s];
        }
        __syncthreads();
    }

    if (t == 0) {
        float loss1_1 = rA[0] / N_ELEM;
        float loss1_2 = rB[0] / N_ELEM;
        float loss2_1 = r21[0] / (2.0f * BATCH) / (float)(BATCH * NUM_KPT);
        float loss2_2 = r22[0] / N_ELEM;
        float w0 = weights[0], w1 = weights[1];
        out[0] = (loss1_1 + loss2_1) * w0 + (loss1_2 + 5.0f * loss2_2) * w1;
        g_count = 0;                           // reset for next graph replay
    }
}

extern "C" void kernel_launch(void* const* d_in, const int* in_sizes, int n_in,
                              void* d_out, int out_size)
{
    const float* o11 = (const float*)d_in[0];
    const float* o12 = (const float*)d_in[1];
    const float* o21 = (const float*)d_in[2];
    const float* o22 = (const float*)d_in[3];
    const float* t1  = (const float*)d_in[4];
    const float* t2  = (const float*)d_in[5];
    const float* w   = (const float*)d_in[6];
    float* out = (float*)d_out;

    hrp_fused<<<NBK, 256>>>(o11, o12, o21, o22, t1, t2, w, out);
}

// round 3
// speedup vs baseline: 1.0215x; 1.0215x over previous
#include <cuda_runtime.h>

#define NUM_KPT 17
#define BATCH   64
#define HWC     6912           // 96*72
#define HW4     1728           // HWC/4
#define NBK     (BATCH * NUM_KPT)   // 1088
#define N_ELEM  7520256.0f     // 64*17*6912

// scratch: per-(b,k) partials (every slot fully written each launch -> no init needed)
__device__ float g_A[NBK];   // sum (out1_1 - t1)^2
__device__ float g_Bv[NBK];  // sum (o12x*t1 - t2x)^2 + (o12y*t1 - t2y)^2
__device__ float g_P[NBK];   // sum (out2_1 - t1)^2
__device__ float g_Q[NBK];   // sum ((o22x-t2x)^2 + (o22y-t2y)^2) * t1^2
__device__ unsigned int g_count = 0;   // arrival counter; reset by last block each launch

__device__ __forceinline__ float warp_sum(float v) {
    #pragma unroll
    for (int o = 16; o > 0; o >>= 1) v += __shfl_xor_sync(0xffffffffu, v, o);
    return v;
}

__global__ __launch_bounds__(256, 8) void hrp_fused(
    const float* __restrict__ o11, const float* __restrict__ o12,
    const float* __restrict__ o21, const float* __restrict__ o22,
    const float* __restrict__ t1,  const float* __restrict__ t2,
    const float* __restrict__ weights, float* __restrict__ out)
{
    const int bk = blockIdx.x;                 // 0..1087
    const int b  = bk / NUM_KPT;
    const int k  = bk % NUM_KPT;

    const size_t base1 = (size_t)bk * HW4;                          // K-channel tensors
    const size_t basex = ((size_t)b * (2 * NUM_KPT) + k) * HW4;     // 2K tensors, x half
    const size_t basey = basex + (size_t)NUM_KPT * HW4;             // y half

    const float4* O11  = (const float4*)o11 + base1;
    const float4* O21  = (const float4*)o21 + base1;
    const float4* T1   = (const float4*)t1  + base1;
    const float4* O12x = (const float4*)o12 + basex;
    const float4* O12y = (const float4*)o12 + basey;
    const float4* O22x = (const float4*)o22 + basex;
    const float4* O22y = (const float4*)o22 + basey;
    const float4* T2x  = (const float4*)t2  + basex;
    const float4* T2y  = (const float4*)t2  + basey;

    float accA = 0.f, accB = 0.f, accP = 0.f, accQ = 0.f;

    for (int i = threadIdx.x; i < HW4; i += 256) {
        float4 v11  = O11[i];
        float4 vt1  = T1[i];
        float4 v21  = O21[i];
        float4 v12x = O12x[i];
        float4 v12y = O12y[i];
        float4 v22x = O22x[i];
        float4 v22y = O22y[i];
        float4 vt2x = T2x[i];
        float4 vt2y = T2y[i];

        const float* p11  = &v11.x;
        const float* pt1  = &vt1.x;
        const float* p21  = &v21.x;
        const float* p12x = &v12x.x;
        const float* p12y = &v12y.x;
        const float* p22x = &v22x.x;
        const float* p22y = &v22y.x;
        const float* pt2x = &vt2x.x;
        const float* pt2y = &vt2y.x;

        #pragma unroll
        for (int l = 0; l < 4; l++) {
            float t  = pt1[l];
            float d1 = p11[l] - t;                 accA = fmaf(d1, d1, accA);
            float ex = fmaf(p12x[l], t, -pt2x[l]); accB = fmaf(ex, ex, accB);
            float ey = fmaf(p12y[l], t, -pt2y[l]); accB = fmaf(ey, ey, accB);
            float d2 = p21[l] - t;                 accP = fmaf(d2, d2, accP);
            float fx = p22x[l] - pt2x[l];
            float fy = p22y[l] - pt2y[l];
            float s  = fmaf(fx, fx, fy * fy);
            accQ = fmaf(s, t * t, accQ);
        }
    }

    // block reduce (8 warps)
    __shared__ float sA[8], sB[8], sP8[8], sQ8[8];
    accA = warp_sum(accA); accB = warp_sum(accB);
    accP = warp_sum(accP); accQ = warp_sum(accQ);
    const int wid = threadIdx.x >> 5, lid = threadIdx.x & 31;
    if (lid == 0) { sA[wid] = accA; sB[wid] = accB; sP8[wid] = accP; sQ8[wid] = accQ; }
    __syncthreads();

    __shared__ bool isLast;
    if (threadIdx.x == 0) {
        float a = 0.f, bb = 0.f, p = 0.f, q = 0.f;
        #pragma unroll
        for (int w = 0; w < 8; w++) { a += sA[w]; bb += sB[w]; p += sP8[w]; q += sQ8[w]; }
        g_A[bk] = a; g_Bv[bk] = bb; g_P[bk] = p; g_Q[bk] = q;
        __threadfence();                       // publish partials before arrival
        unsigned int prev = atomicAdd(&g_count, 1u);
        isLast = (prev == NBK - 1u);
    }
    __syncthreads();
    if (!isLast) return;

    // ---- final reduction: only the last-arriving block runs this ----
    const int t = threadIdx.x;

    __shared__ float sP[NBK];   // staged per-(b,k) P
    __shared__ float sQ[NBK];   // staged per-(b,k) Q

    float a = 0.f, bb = 0.f;
    for (int i = t; i < NBK; i += 256) {
        sP[i] = g_P[i];
        sQ[i] = g_Q[i];
        a  += g_A[i];
        bb += g_Bv[i];
    }
    __syncthreads();

    // rank-based top-8 per batch: fully unrolled, register+smem only,
    // matches jax.lax.top_k (largest values; lower index wins ties)
    float l21 = 0.f, l22 = 0.f;
    if (t < BATCH) {
        const float* pv = &sP[t * NUM_KPT];
        #pragma unroll
        for (int kk = 0; kk < NUM_KPT; kk++) {
            float v = pv[kk];
            int r = 0;
            #pragma unroll
            for (int j = 0; j < NUM_KPT; j++) {
                float u = pv[j];
                r += (u > v) || (u == v && j < kk);
            }
            if (r < NUM_KPT / 2) {   // r < 8 -> selected
                l21 += v;
                l22 += sQ[t * NUM_KPT + kk];
            }
        }
    }
    __syncthreads();

    // final 4-way block reduction (reuse sP as scratch: 4 x 256 floats)
    float* rA  = sP;
    float* rB  = sP + 256;
    float* r21 = sP + 512;
    float* r22 = sP + 768;
    rA[t] = a; rB[t] = bb; r21[t] = l21; r22[t] = l22;
    __syncthreads();
    #pragma unroll
    for (int s = 128; s > 0; s >>= 1) {
        if (t < s) {
            rA[t]  += rA[t + s];
            rB[t]  += rB[t + s];
            r21[t] += r21[t + s];
            r22[t] += r22[t + s];
        }
        __syncthreads();
    }

    if (t == 0) {
        float loss1_1 = rA[0] / N_ELEM;
        float loss1_2 = rB[0] / N_ELEM;
        float loss2_1 = r21[0] / (2.0f * BATCH) / (float)(BATCH * NUM_KPT);
        float loss2_2 = r22[0] / N_ELEM;
        float w0 = weights[0], w1 = weights[1];
        out[0] = (loss1_1 + loss2_1) * w0 + (loss1_2 + 5.0f * loss2_2) * w1;
        g_count = 0;                           // reset for next graph replay
    }
}

extern "C" void kernel_launch(void* const* d_in, const int* in_sizes, int n_in,
                              void* d_out, int out_size)
{
    const float* o11 = (const float*)d_in[0];
    const float* o12 = (const float*)d_in[1];
    const float* o21 = (const float*)d_in[2];
    const float* o22 = (const float*)d_in[3];
    const float* t1  = (const float*)d_in[4];
    const float* t2  = (const float*)d_in[5];
    const float* w   = (const float*)d_in[6];
    float* out = (float*)d_out;

    hrp_fused<<<NBK, 256>>>(o11, o12, o21, o22, t1, t2, w, out);
}

// round 4
// speedup vs baseline: 1.2266x; 1.2008x over previous
#include <cuda_runtime.h>

#define NUM_KPT 17
#define BATCH   64
#define HWC     6912           // 96*72
#define HW4     1728           // HWC/4
#define NBK     (BATCH * NUM_KPT)   // 1088
#define N_ELEM  7520256.0f     // 64*17*6912

// scratch: per-(b,k) partials (every slot fully written each launch -> no init needed)
__device__ float g_A[NBK];   // sum (out1_1 - t1)^2
__device__ float g_Bv[NBK];  // sum (o12x*t1 - t2x)^2 + (o12y*t1 - t2y)^2
__device__ float g_P[NBK];   // sum (out2_1 - t1)^2
__device__ float g_Q[NBK];   // sum ((o22x-t2x)^2 + (o22y-t2y)^2) * t1^2
__device__ unsigned int g_count = 0;   // arrival counter; reset by last block each launch

__device__ __forceinline__ float warp_sum(float v) {
    #pragma unroll
    for (int o = 16; o > 0; o >>= 1) v += __shfl_xor_sync(0xffffffffu, v, o);
    return v;
}

// min-blocks 4 -> 64 regs/thread: enough to front-batch all 9 float4 loads
// (36 regs of payload) per iteration for high per-thread MLP.
__global__ __launch_bounds__(256, 4) void hrp_fused(
    const float* __restrict__ o11, const float* __restrict__ o12,
    const float* __restrict__ o21, const float* __restrict__ o22,
    const float* __restrict__ t1,  const float* __restrict__ t2,
    const float* __restrict__ weights, float* __restrict__ out)
{
    const int bk = blockIdx.x;                 // 0..1087
    const int b  = bk / NUM_KPT;
    const int k  = bk % NUM_KPT;

    const size_t base1 = (size_t)bk * HW4;                          // K-channel tensors
    const size_t basex = ((size_t)b * (2 * NUM_KPT) + k) * HW4;     // 2K tensors, x half
    const size_t basey = basex + (size_t)NUM_KPT * HW4;             // y half

    const float4* O11  = (const float4*)o11 + base1;
    const float4* O21  = (const float4*)o21 + base1;
    const float4* T1   = (const float4*)t1  + base1;
    const float4* O12x = (const float4*)o12 + basex;
    const float4* O12y = (const float4*)o12 + basey;
    const float4* O22x = (const float4*)o22 + basex;
    const float4* O22y = (const float4*)o22 + basey;
    const float4* T2x  = (const float4*)t2  + basex;
    const float4* T2y  = (const float4*)t2  + basey;

    float accA = 0.f, accB = 0.f, accP = 0.f, accQ = 0.f;

    for (int i = threadIdx.x; i < HW4; i += 256) {
        float4 v11  = O11[i];
        float4 vt1  = T1[i];
        float4 v21  = O21[i];
        float4 v12x = O12x[i];
        float4 v12y = O12y[i];
        float4 v22x = O22x[i];
        float4 v22y = O22y[i];
        float4 vt2x = T2x[i];
        float4 vt2y = T2y[i];

        const float* p11  = &v11.x;
        const float* pt1  = &vt1.x;
        const float* p21  = &v21.x;
        const float* p12x = &v12x.x;
        const float* p12y = &v12y.x;
        const float* p22x = &v22x.x;
        const float* p22y = &v22y.x;
        const float* pt2x = &vt2x.x;
        const float* pt2y = &vt2y.x;

        #pragma unroll
        for (int l = 0; l < 4; l++) {
            float t  = pt1[l];
            float d1 = p11[l] - t;                 accA = fmaf(d1, d1, accA);
            float ex = fmaf(p12x[l], t, -pt2x[l]); accB = fmaf(ex, ex, accB);
            float ey = fmaf(p12y[l], t, -pt2y[l]); accB = fmaf(ey, ey, accB);
            float d2 = p21[l] - t;                 accP = fmaf(d2, d2, accP);
            float fx = p22x[l] - pt2x[l];
            float fy = p22y[l] - pt2y[l];
            float s  = fmaf(fx, fx, fy * fy);
            accQ = fmaf(s, t * t, accQ);
        }
    }

    // block reduce (8 warps)
    __shared__ float sA[8], sB[8], sP8[8], sQ8[8];
    accA = warp_sum(accA); accB = warp_sum(accB);
    accP = warp_sum(accP); accQ = warp_sum(accQ);
    const int wid = threadIdx.x >> 5, lid = threadIdx.x & 31;
    if (lid == 0) { sA[wid] = accA; sB[wid] = accB; sP8[wid] = accP; sQ8[wid] = accQ; }
    __syncthreads();

    __shared__ bool isLast;
    if (threadIdx.x == 0) {
        float a = 0.f, bb = 0.f, p = 0.f, q = 0.f;
        #pragma unroll
        for (int w = 0; w < 8; w++) { a += sA[w]; bb += sB[w]; p += sP8[w]; q += sQ8[w]; }
        g_A[bk] = a; g_Bv[bk] = bb; g_P[bk] = p; g_Q[bk] = q;
        __threadfence();                       // publish partials before arrival
        unsigned int prev = atomicAdd(&g_count, 1u);
        isLast = (prev == NBK - 1u);
    }
    __syncthreads();
    if (!isLast) return;

    // ---- final reduction: only the last-arriving block runs this ----
    const int t = threadIdx.x;

    __shared__ float sP[NBK];   // staged per-(b,k) P
    __shared__ float sQ[NBK];   // staged per-(b,k) Q

    float a = 0.f, bb = 0.f;
    for (int i = t; i < NBK; i += 256) {
        sP[i] = g_P[i];
        sQ[i] = g_Q[i];
        a  += g_A[i];
        bb += g_Bv[i];
    }
    __syncthreads();

    // rank-based top-8 per batch: fully unrolled, register+smem only,
    // matches jax.lax.top_k (largest values; lower index wins ties)
    float l21 = 0.f, l22 = 0.f;
    if (t < BATCH) {
        const float* pv = &sP[t * NUM_KPT];
        #pragma unroll
        for (int kk = 0; kk < NUM_KPT; kk++) {
            float v = pv[kk];
            int r = 0;
            #pragma unroll
            for (int j = 0; j < NUM_KPT; j++) {
                float u = pv[j];
                r += (u > v) || (u == v && j < kk);
            }
            if (r < NUM_KPT / 2) {   // r < 8 -> selected
                l21 += v;
                l22 += sQ[t * NUM_KPT + kk];
            }
        }
    }
    __syncthreads();

    // final 4-way block reduction (reuse sP as scratch: 4 x 256 floats)
    float* rA  = sP;
    float* rB  = sP + 256;
    float* r21 = sP + 512;
    float* r22 = sP + 768;
    rA[t] = a; rB[t] = bb; r21[t] = l21; r22[t] = l22;
    __syncthreads();
    #pragma unroll
    for (int s = 128; s > 0; s >>= 1) {
        if (t < s) {
            rA[t]  += rA[t + s];
            rB[t]  += rB[t + s];
            r21[t] += r21[t + s];
            r22[t] += r22[t + s];
        }
        __syncthreads();
    }

    if (t == 0) {
        float loss1_1 = rA[0] / N_ELEM;
        float loss1_2 = rB[0] / N_ELEM;
        float loss2_1 = r21[0] / (2.0f * BATCH) / (float)(BATCH * NUM_KPT);
        float loss2_2 = r22[0] / N_ELEM;
        float w0 = weights[0], w1 = weights[1];
        out[0] = (loss1_1 + loss2_1) * w0 + (loss1_2 + 5.0f * loss2_2) * w1;
        g_count = 0;                           // reset for next graph replay
    }
}

extern "C" void kernel_launch(void* const* d_in, const int* in_sizes, int n_in,
                              void* d_out, int out_size)
{
    const float* o11 = (const float*)d_in[0];
    const float* o12 = (const float*)d_in[1];
    const float* o21 = (const float*)d_in[2];
    const float* o22 = (const float*)d_in[3];
    const float* t1  = (const float*)d_in[4];
    const float* t2  = (const float*)d_in[5];
    const float* w   = (const float*)d_in[6];
    float* out = (float*)d_out;

    hrp_fused<<<NBK, 256>>>(o11, o12, o21, o22, t1, t2, w, out);
}